// round 10
// baseline (speedup 1.0000x reference)
#include <cuda_runtime.h>
#include <math_constants.h>

// NNLoss: bidirectional 2-D NN loss via uniform-grid spatial binning.
// Kernel 1: per-(set,batch) block-local bin, serpentine cell order.
// Kernel 2: hybrid query — dense warps scan their (small) union box
//           cooperatively (broadcast, uniform control flow); sparse warps
//           fall back to per-lane 3x3; rare lanes ring-expand.

namespace {
constexpr int   Bc   = 64;
constexpr int   Nc   = 2048;
constexpr int   NSB  = 2 * Bc;            // (set, batch) segments = 128
constexpr int   G    = 64;
constexpr int   G2   = G * G;             // 4096 cells
constexpr int   SST  = G2 + 8;            // starts stride (padded)
constexpr float EXT  = 6.0f;
constexpr float CELL = 2.0f * EXT / G;    // 0.1875
constexpr float INVC = (float)G / (2.0f * EXT);
constexpr int   TPB  = 256;
constexpr int   QCH  = Nc / TPB;          // 8 query chunks per (dir,b)
constexpr unsigned IDXMASK = 2047u;       // low 11 bits carry tile index
constexpr unsigned SENTINEL = 0x7F800000u | IDXMASK;  // +INF | idx-sat
constexpr int   COOP_MAX_ROWS = 4;        // grown union box row limit
constexpr int   COOP_MAX_PTS  = 160;      // grown union box point limit
}

__device__ unsigned short g_start[NSB * SST];   // exclusive cell starts (+total)
__device__ float2         g_sorted[NSB * Nc];   // cell-sorted {x, y}

__device__ __forceinline__ int cell_of(float v) {
    int c = __float2int_rd((v + EXT) * INVC);
    return min(G - 1, max(0, c));
}
// serpentine cell id: odd rows reversed so consecutive cells stay adjacent
__device__ __forceinline__ int cell_id(int x, int y) {
    return y * G + ((y & 1) ? (G - 1 - x) : x);
}

// ---------------- Kernel 1: block-local binning ----------------
__global__ __launch_bounds__(TPB)
void bin_kernel(const float* __restrict__ preds,
                const float* __restrict__ targs,
                float* __restrict__ out)
{
    __shared__ unsigned int scnt[G2];      // counts -> scatter cursors
    __shared__ float2 pts[Nc];
    __shared__ unsigned int part[TPB];

    const int sb  = blockIdx.x;            // set*64 + b
    const int set = sb >> 6;
    const int b   = sb & (Bc - 1);
    if (sb == 0 && threadIdx.x == 0) out[0] = 0.0f;

    const float4* src = reinterpret_cast<const float4*>(set ? targs : preds)
                      + (size_t)b * Nc;
#pragma unroll
    for (int i = 0; i < Nc / TPB; ++i) {
        float4 p = src[threadIdx.x + i * TPB];
        pts[threadIdx.x + i * TPB] = make_float2(p.x, p.y);
    }
#pragma unroll
    for (int i = 0; i < G2 / TPB; ++i)
        scnt[threadIdx.x + i * TPB] = 0u;
    __syncthreads();

#pragma unroll
    for (int i = 0; i < Nc / TPB; ++i) {
        float2 p = pts[threadIdx.x + i * TPB];
        atomicAdd(&scnt[cell_id(cell_of(p.x), cell_of(p.y))], 1u);
    }
    __syncthreads();

    // block exclusive scan of 4096 counters
    unsigned int v[16], sum = 0;
    const int base = threadIdx.x * 16;
#pragma unroll
    for (int i = 0; i < 16; ++i) { v[i] = scnt[base + i]; sum += v[i]; }
    part[threadIdx.x] = sum;
    __syncthreads();
    for (int off = 1; off < TPB; off <<= 1) {
        unsigned int a = (threadIdx.x >= off) ? part[threadIdx.x - off] : 0u;
        __syncthreads();
        if (threadIdx.x >= off) part[threadIdx.x] += a;
        __syncthreads();
    }
    unsigned int run = threadIdx.x ? part[threadIdx.x - 1] : 0u;
    unsigned short* st = g_start + sb * SST;
#pragma unroll
    for (int i = 0; i < 16; ++i) {
        scnt[base + i] = run;                       // scatter cursor
        st[base + i]   = (unsigned short)run;
        run += v[i];
    }
    if (threadIdx.x == TPB - 1) st[G2] = (unsigned short)run;   // 2048
    __syncthreads();

    float2* dst = g_sorted + (size_t)sb * Nc;
#pragma unroll
    for (int i = 0; i < Nc / TPB; ++i) {
        float2 p = pts[threadIdx.x + i * TPB];
        unsigned int pos =
            atomicAdd(&scnt[cell_id(cell_of(p.x), cell_of(p.y))], 1u);
        dst[pos] = p;
    }
}

// ---------------- Kernel 2: hybrid query ----------------
__global__ __launch_bounds__(TPB)
void query_kernel(const float* __restrict__ subcoef, float* __restrict__ out)
{
    __shared__ float2 tile[Nc];                  // db points (cell-sorted)
    __shared__ unsigned short sst[G2 + 1];       // db cell starts
    __shared__ float red[TPB / 32];

    int bid = blockIdx.x;
    const int chunk = bid & (QCH - 1);  bid >>= 3;
    const int b     = bid & (Bc - 1);   bid >>= 6;
    const int dir   = bid;                       // 0: preds->targs, 1: targs->preds
    const int qsb = dir * Bc + b;                // query set (set0 = preds)
    const int dsb = (1 - dir) * Bc + b;          // db set

    for (int t = threadIdx.x; t < Nc; t += TPB)  tile[t] = g_sorted[(size_t)dsb * Nc + t];
    for (int t = threadIdx.x; t <= G2; t += TPB) sst[t]  = g_start[dsb * SST + t];
    __syncthreads();

    // queries = own set's sorted points -> warp lanes are cell-adjacent
    float2 q = g_sorted[(size_t)qsb * Nc + chunk * TPB + threadIdx.x];
    const float qx = q.x, qy = q.y;
    const int cx = cell_of(qx), cy = cell_of(qy);

    // packed running argmin: high 21 bits = truncated d^2 bits, low 11 = index
    unsigned mn = SENTINEL;

    auto eval = [&](int j) {
        float2 t = tile[j];
        float dx = t.x - qx, dy = t.y - qy;
        float s = fmaf(dx, dx, dy * dy);
        unsigned pk = (__float_as_uint(s) & ~IDXMASK) | (unsigned)j;
        mn = min(mn, pk);
    };
    auto scan = [&](int j, int je) {
        for (; j + 3 < je; j += 4) { eval(j); eval(j + 1); eval(j + 2); eval(j + 3); }
        for (; j < je; ++j) eval(j);
    };
    // serpentine-aware contiguous span for cells [xa..xb] of row y
    auto span_of = [&](int y, int xa, int xb, int& lo, int& hi) {
        int base = y * G;
        if (y & 1) { lo = base + (G - 1 - xb); hi = base + (G - 1 - xa); }
        else       { lo = base + xa;           hi = base + xb;           }
    };

    // warp union box grown by 1 (uniform)
    const int minx = __reduce_min_sync(0xffffffffu, cx);
    const int maxx = __reduce_max_sync(0xffffffffu, cx);
    const int miny = __reduce_min_sync(0xffffffffu, cy);
    const int maxy = __reduce_max_sync(0xffffffffu, cy);
    const int xa1 = max(minx - 1, 0), xb1 = min(maxx + 1, G - 1);
    const int ya1 = max(miny - 1, 0), yb1 = min(maxy + 1, G - 1);

    bool coop = false;
    if (yb1 - ya1 + 1 <= COOP_MAX_ROWS) {
        int cnt = 0;
        for (int y = ya1; y <= yb1; ++y) {
            int lo, hi; span_of(y, xa1, xb1, lo, hi);
            cnt += (int)sst[hi + 1] - (int)sst[lo];
        }
        coop = (cnt <= COOP_MAX_PTS);            // warp-uniform
    }

    if (coop) {
        // cooperative: all lanes scan identical spans (LDS broadcast).
        // Box covers Chebyshev<=1 of every lane's cell.
        for (int y = ya1; y <= yb1; ++y) {
            int lo, hi; span_of(y, xa1, xb1, lo, hi);
            scan(sst[lo], sst[hi + 1]);
        }
    } else {
        // per-lane 3x3 box
        const int xa = max(cx - 1, 0), xb = min(cx + 1, G - 1);
        const int ya = max(cy - 1, 0), yb = min(cy + 1, G - 1);
        for (int y = ya; y <= yb; ++y) {
            int lo, hi; span_of(y, xa, xb, lo, hi);
            scan(sst[lo], sst[hi + 1]);
        }
    }

    // exit bound: all cells at Chebyshev<=1 of the lane's cell are scanned,
    // so unscanned points are >= CELL away. Empty box -> +INF -> expand.
    float best = __uint_as_float(mn & ~IDXMASK);
    if (__any_sync(0xffffffffu, best > CELL * CELL)) {
        if (best > CELL * CELL) {
            for (int k = 2; k < G; ++k) {        // ring k: d >= (k-1)*CELL
                float bd = (float)(k - 1) * CELL;
                if (best <= bd * bd) break;
                const int exa = max(cx - k, 0), exb = min(cx + k, G - 1);
                const int eya = max(cy - k, 0), eyb = min(cy + k, G - 1);
                for (int y = eya; y <= eyb; ++y) {
                    if (y == cy - k || y == cy + k) {
                        int lo, hi; span_of(y, exa, exb, lo, hi);
                        scan(sst[lo], sst[hi + 1]);
                    } else {
                        if (cx - k >= 0) {
                            int lo, hi; span_of(y, cx - k, cx - k, lo, hi);
                            scan(sst[lo], sst[hi + 1]);
                        }
                        if (cx + k < G) {
                            int lo, hi; span_of(y, cx + k, cx + k, lo, hi);
                            scan(sst[lo], sst[hi + 1]);
                        }
                    }
                }
                best = __uint_as_float(mn & ~IDXMASK);
            }
        }
    }

    float2 w = tile[mn & IDXMASK];
    const float cA = dir ? 1.0f : subcoef[0];
    const float cB = dir ? 1.0f : subcoef[1];
    float contrib = fabsf(qx - w.x) * cA + fabsf(qy - w.y) * cB;

#pragma unroll
    for (int o = 16; o > 0; o >>= 1)
        contrib += __shfl_down_sync(0xffffffffu, contrib, o);
    if ((threadIdx.x & 31) == 0) red[threadIdx.x >> 5] = contrib;
    __syncthreads();
    if (threadIdx.x < 32) {
        float v = (threadIdx.x < TPB / 32) ? red[threadIdx.x] : 0.0f;
#pragma unroll
        for (int o = 4; o > 0; o >>= 1)
            v += __shfl_down_sync(0x000000ffu, v, o);
        if (threadIdx.x == 0) atomicAdd(out, v);
    }
}

extern "C" void kernel_launch(void* const* d_in, const int* in_sizes, int n_in,
                              void* d_out, int out_size)
{
    const float* preds   = (const float*)d_in[0];
    const float* targs   = (const float*)d_in[1];
    const float* subcoef = (const float*)d_in[2];
    float* out = (float*)d_out;

    bin_kernel  <<<NSB, TPB>>>(preds, targs, out);          // 128 blocks
    query_kernel<<<2 * Bc * QCH, TPB>>>(subcoef, out);      // 1024 blocks
}